// round 1
// baseline (speedup 1.0000x reference)
#include <cuda_runtime.h>
#include <math.h>

#define N_NODES 100000
#define N_EDGES 1600000
#define DIN 512
#define DH 128
#define DOUT 40
#define TOT_EDGES (N_EDGES + N_NODES)

// ---------------- scratch (device globals; no runtime allocation) -------------
__device__ int   g_deg[N_NODES];
__device__ int   g_off[N_NODES + 1];
__device__ int   g_cur[N_NODES];
__device__ float g_dinv[N_NODES];
__device__ int   g_csr_src[TOT_EDGES];
__device__ float g_csr_w[TOT_EDGES];
__device__ float g_h1[(size_t)N_NODES * DH];   // X @ W1 (pre-agg)
__device__ float g_a1[(size_t)N_NODES * DH];   // relu(agg(h1) + b1)
__device__ float g_h2[(size_t)N_NODES * DOUT]; // a1 @ W2 (pre-agg)

// ---------------- degree init / histogram -------------------------------------
__global__ void init_kernel() {
    int i = blockIdx.x * blockDim.x + threadIdx.x;
    if (i < N_NODES) { g_deg[i] = 1; g_cur[i] = 0; }   // 1 = self-loop
}

__global__ void hist_kernel(const int* __restrict__ dst) {
    int e = blockIdx.x * blockDim.x + threadIdx.x;
    if (e < N_EDGES) atomicAdd(&g_deg[dst[e]], 1);
}

// single-block exclusive scan of g_deg -> g_off, plus dinv = rsqrt(deg)
__global__ void scan_kernel() {
    __shared__ int wsum[32];
    __shared__ int chunk_total;
    const int tid = threadIdx.x;
    const int lane = tid & 31, wp = tid >> 5;
    int carry = 0;
    for (int base = 0; base < N_NODES; base += 1024) {
        int i = base + tid;
        int v = (i < N_NODES) ? g_deg[i] : 0;
        int x = v;
        #pragma unroll
        for (int o = 1; o < 32; o <<= 1) {
            int t = __shfl_up_sync(0xffffffffu, x, o);
            if (lane >= o) x += t;
        }
        if (lane == 31) wsum[wp] = x;
        __syncthreads();
        if (wp == 0) {
            int s = wsum[lane];
            int y = s;
            #pragma unroll
            for (int o = 1; o < 32; o <<= 1) {
                int t = __shfl_up_sync(0xffffffffu, y, o);
                if (lane >= o) y += t;
            }
            wsum[lane] = y - s;           // exclusive warp offsets
            if (lane == 31) chunk_total = y;
        }
        __syncthreads();
        int incl = x + wsum[wp];
        if (i < N_NODES) {
            g_off[i]  = carry + incl - v;  // exclusive scan
            g_dinv[i] = rsqrtf((float)v);
        }
        carry += chunk_total;
        __syncthreads();
    }
    if (tid == 0) g_off[N_NODES] = carry;
}

__global__ void scatter_kernel(const int* __restrict__ src, const int* __restrict__ dst) {
    int e = blockIdx.x * blockDim.x + threadIdx.x;
    if (e >= TOT_EDGES) return;
    int s, d;
    if (e < N_EDGES) { s = src[e]; d = dst[e]; }
    else             { s = d = e - N_EDGES; }          // self-loop
    int pos = g_off[d] + atomicAdd(&g_cur[d], 1);
    g_csr_src[pos] = s;
    g_csr_w[pos]   = g_dinv[s] * g_dinv[d];
}

// ---------------- GEMM1: H1[100k,128] = X[100k,512] @ W1[512,128] --------------
// 128x128 block tile, BK=8, 256 threads, 8x8 per thread (fp32 SIMT)
__global__ __launch_bounds__(256) void gemm1_kernel(const float* __restrict__ X,
                                                    const float* __restrict__ W,
                                                    float* __restrict__ H) {
    __shared__ float As[8][128];
    __shared__ float Bs[8][128];
    const int tid  = threadIdx.x;
    const int row0 = blockIdx.x * 128;
    const int tx = tid & 15;       // 0..15  -> 8 cols each
    const int ty = tid >> 4;       // 0..15  -> 8 rows each

    const int arow = tid >> 1;          // 0..127
    const int acol = (tid & 1) * 4;     // 0 or 4
    const int brow = tid >> 5;          // 0..7
    const int bcol = (tid & 31) * 4;    // 0..124

    float acc[8][8];
    #pragma unroll
    for (int i = 0; i < 8; i++)
        #pragma unroll
        for (int j = 0; j < 8; j++) acc[i][j] = 0.f;

    const int grow = row0 + arow;
    for (int k0 = 0; k0 < DIN; k0 += 8) {
        float4 av = make_float4(0.f, 0.f, 0.f, 0.f);
        if (grow < N_NODES)
            av = *reinterpret_cast<const float4*>(X + (size_t)grow * DIN + k0 + acol);
        As[acol + 0][arow] = av.x;
        As[acol + 1][arow] = av.y;
        As[acol + 2][arow] = av.z;
        As[acol + 3][arow] = av.w;
        *reinterpret_cast<float4*>(&Bs[brow][bcol]) =
            *reinterpret_cast<const float4*>(W + (size_t)(k0 + brow) * DH + bcol);
        __syncthreads();

        #pragma unroll
        for (int k = 0; k < 8; k++) {
            float4 a0 = *reinterpret_cast<const float4*>(&As[k][ty * 8]);
            float4 a1 = *reinterpret_cast<const float4*>(&As[k][ty * 8 + 4]);
            float4 b0 = *reinterpret_cast<const float4*>(&Bs[k][tx * 8]);
            float4 b1 = *reinterpret_cast<const float4*>(&Bs[k][tx * 8 + 4]);
            float a[8] = {a0.x, a0.y, a0.z, a0.w, a1.x, a1.y, a1.z, a1.w};
            float b[8] = {b0.x, b0.y, b0.z, b0.w, b1.x, b1.y, b1.z, b1.w};
            #pragma unroll
            for (int i = 0; i < 8; i++)
                #pragma unroll
                for (int j = 0; j < 8; j++) acc[i][j] += a[i] * b[j];
        }
        __syncthreads();
    }

    #pragma unroll
    for (int i = 0; i < 8; i++) {
        int r = row0 + ty * 8 + i;
        if (r < N_NODES) {
            float* out = H + (size_t)r * DH + tx * 8;
            *reinterpret_cast<float4*>(out)     = make_float4(acc[i][0], acc[i][1], acc[i][2], acc[i][3]);
            *reinterpret_cast<float4*>(out + 4) = make_float4(acc[i][4], acc[i][5], acc[i][6], acc[i][7]);
        }
    }
}

// ---------------- Agg1: a1 = relu(A_hat @ h1 + b1), warp per node --------------
__global__ void agg1_kernel(const float* __restrict__ b1) {
    int gw = (blockIdx.x * blockDim.x + threadIdx.x) >> 5;
    int lane = threadIdx.x & 31;
    if (gw >= N_NODES) return;
    int beg = g_off[gw], end = g_off[gw + 1];
    float4 acc = make_float4(0.f, 0.f, 0.f, 0.f);
    for (int p = beg; p < end; ++p) {
        int   s = g_csr_src[p];
        float w = g_csr_w[p];
        float4 hv = *reinterpret_cast<const float4*>(g_h1 + (size_t)s * DH + lane * 4);
        acc.x += w * hv.x; acc.y += w * hv.y; acc.z += w * hv.z; acc.w += w * hv.w;
    }
    float4 bv = *reinterpret_cast<const float4*>(b1 + lane * 4);
    acc.x = fmaxf(acc.x + bv.x, 0.f);
    acc.y = fmaxf(acc.y + bv.y, 0.f);
    acc.z = fmaxf(acc.z + bv.z, 0.f);
    acc.w = fmaxf(acc.w + bv.w, 0.f);
    *reinterpret_cast<float4*>(g_a1 + (size_t)gw * DH + lane * 4) = acc;
}

// ---------------- GEMM2: h2[100k,40] = a1[100k,128] @ W2[128,40] ---------------
// blockDim 128; block covers 128 rows; thread = (rowgroup of 4 rows) x (10 cols)
__global__ __launch_bounds__(128) void gemm2_kernel(const float* __restrict__ W2) {
    __shared__ float sW[DH * DOUT];   // 20 KB, [k][c]
    const int tid = threadIdx.x;
    #pragma unroll
    for (int j = 0; j < (DH * DOUT) / 128; j++)
        sW[tid + j * 128] = W2[tid + j * 128];
    __syncthreads();

    const int row0 = blockIdx.x * 128;
    const int rg = tid >> 2;          // 0..31
    const int cg = tid & 3;           // 0..3 -> cols cg*10..+9
    float acc[4][10];
    #pragma unroll
    for (int i = 0; i < 4; i++)
        #pragma unroll
        for (int j = 0; j < 10; j++) acc[i][j] = 0.f;

    int r[4];
    #pragma unroll
    for (int i = 0; i < 4; i++) r[i] = row0 + rg * 4 + i;

    for (int k = 0; k < DH; k++) {
        float a[4];
        #pragma unroll
        for (int i = 0; i < 4; i++)
            a[i] = (r[i] < N_NODES) ? __ldg(g_a1 + (size_t)r[i] * DH + k) : 0.f;
        const float* wrow = &sW[k * DOUT + cg * 10];
        #pragma unroll
        for (int j = 0; j < 10; j++) {
            float w = wrow[j];
            #pragma unroll
            for (int i = 0; i < 4; i++) acc[i][j] += a[i] * w;
        }
    }
    #pragma unroll
    for (int i = 0; i < 4; i++) {
        if (r[i] < N_NODES) {
            float* out = g_h2 + (size_t)r[i] * DOUT + cg * 10;
            #pragma unroll
            for (int j = 0; j < 10; j++) out[j] = acc[i][j];
        }
    }
}

// ---------------- Agg2: out_h = A_hat @ h2 + b2, warp per node -----------------
__global__ void agg2_kernel(const float* __restrict__ b2, float* __restrict__ out) {
    int gw = (blockIdx.x * blockDim.x + threadIdx.x) >> 5;
    int lane = threadIdx.x & 31;
    if (gw >= N_NODES) return;
    int beg = g_off[gw], end = g_off[gw + 1];
    float acc0 = 0.f, acc1 = 0.f;
    bool has2 = lane < (DOUT - 32);
    for (int p = beg; p < end; ++p) {
        int   s = g_csr_src[p];
        float w = g_csr_w[p];
        const float* row = g_h2 + (size_t)s * DOUT;
        acc0 += w * row[lane];
        if (has2) acc1 += w * row[32 + lane];
    }
    float* orow = out + (size_t)gw * DOUT;
    orow[lane] = acc0 + b2[lane];
    if (has2) orow[32 + lane] = acc1 + b2[32 + lane];
}

// ---------------- log_softmax over DOUT=40, warp per node ----------------------
__global__ void logsoftmax_kernel(const float* __restrict__ h, float* __restrict__ out) {
    int gw = (blockIdx.x * blockDim.x + threadIdx.x) >> 5;
    int lane = threadIdx.x & 31;
    if (gw >= N_NODES) return;
    const float* row = h + (size_t)gw * DOUT;
    bool has2 = lane < (DOUT - 32);
    float v0 = row[lane];
    float v1 = has2 ? row[32 + lane] : -INFINITY;
    float m = fmaxf(v0, v1);
    #pragma unroll
    for (int o = 16; o > 0; o >>= 1) m = fmaxf(m, __shfl_xor_sync(0xffffffffu, m, o));
    float e = expf(v0 - m) + (has2 ? expf(v1 - m) : 0.f);
    #pragma unroll
    for (int o = 16; o > 0; o >>= 1) e += __shfl_xor_sync(0xffffffffu, e, o);
    float lse = m + logf(e);
    float* orow = out + (size_t)gw * DOUT;
    orow[lane] = v0 - lse;
    if (has2) orow[32 + lane] = v1 - lse;
}

// ---------------- launch --------------------------------------------------------
extern "C" void kernel_launch(void* const* d_in, const int* in_sizes, int n_in,
                              void* d_out, int out_size) {
    const float* x   = (const float*)d_in[0];
    const int*   ei  = (const int*)  d_in[1];   // [2,E] row-major
    const float* W1  = (const float*)d_in[2];
    const float* b1  = (const float*)d_in[3];
    const float* W2  = (const float*)d_in[4];
    const float* b2  = (const float*)d_in[5];
    float* out = (float*)d_out;

    const int* src = ei;
    const int* dst = ei + N_EDGES;

    float* h1;  cudaGetSymbolAddress((void**)&h1, g_h1);

    init_kernel<<<(N_NODES + 255) / 256, 256>>>();
    hist_kernel<<<(N_EDGES + 255) / 256, 256>>>(dst);
    scan_kernel<<<1, 1024>>>();
    scatter_kernel<<<(TOT_EDGES + 255) / 256, 256>>>(src, dst);

    gemm1_kernel<<<(N_NODES + 127) / 128, 256>>>(x, W1, h1);
    agg1_kernel<<<(N_NODES * 32 + 255) / 256, 256>>>(b1);
    gemm2_kernel<<<(N_NODES + 127) / 128, 128>>>(W2);

    // out = [h (N*DOUT) | log_softmax(h) (N*DOUT)]
    agg2_kernel<<<(N_NODES * 32 + 255) / 256, 256>>>(b2, out);
    if (out_size >= 2 * N_NODES * DOUT) {
        logsoftmax_kernel<<<(N_NODES * 32 + 255) / 256, 256>>>(out, out + (size_t)N_NODES * DOUT);
    }
}

// round 3
// speedup vs baseline: 1.4787x; 1.4787x over previous
#include <cuda_runtime.h>
#include <cuda_bf16.h>
#include <math.h>
#include <stdint.h>

#define N_NODES 100000
#define N_EDGES 1600000
#define DIN 512
#define DH 128
#define DOUT 40
#define TOT_EDGES (N_EDGES + N_NODES)

// ---------------- scratch (device globals; no runtime allocation) -------------
__device__ int   g_deg[N_NODES];
__device__ int   g_off[N_NODES + 1];
__device__ int   g_cur[N_NODES];
__device__ float g_dinv[N_NODES];
__device__ int   g_csr_src[TOT_EDGES];
__device__ float g_csr_w[TOT_EDGES];
__device__ __align__(16) float g_h1[(size_t)N_NODES * DH];   // X @ W1 (pre-agg)
__device__ __align__(16) float g_a1[(size_t)N_NODES * DH];   // relu(agg(h1) + b1)
__device__ __align__(16) float g_h2[(size_t)N_NODES * DOUT]; // a1 @ W2 (pre-agg)
__device__ __align__(16) __nv_bfloat16 g_w1bh[(size_t)DH * DIN]; // W1^T bf16 hi, [n][k]
__device__ __align__(16) __nv_bfloat16 g_w1bl[(size_t)DH * DIN]; // W1^T bf16 lo

// ---------------- helpers -------------------------------------------------------
__device__ __forceinline__ uint32_t smem_u32(const void* p) {
    uint32_t a;
    asm("{ .reg .u64 t; cvta.to.shared.u64 t, %1; cvt.u32.u64 %0, t; }" : "=r"(a) : "l"(p));
    return a;
}

__device__ __forceinline__ uint32_t pack_bf16(__nv_bfloat16 lo16, __nv_bfloat16 hi16) {
    // lo16 -> low half (even k), hi16 -> high half (odd k)
    uint32_t l = (uint32_t)__bfloat16_as_ushort(lo16);
    uint32_t h = (uint32_t)__bfloat16_as_ushort(hi16);
    return l | (h << 16);
}

__device__ __forceinline__ void ldmat4(uint32_t* r, uint32_t addr) {
    asm volatile("ldmatrix.sync.aligned.m8n8.x4.shared.b16 {%0,%1,%2,%3}, [%4];"
                 : "=r"(r[0]), "=r"(r[1]), "=r"(r[2]), "=r"(r[3]) : "r"(addr));
}

__device__ __forceinline__ void mma_bf16(float* c, const uint32_t* a, uint32_t b0, uint32_t b1) {
    asm volatile(
        "mma.sync.aligned.m16n8k16.row.col.f32.bf16.bf16.f32 "
        "{%0,%1,%2,%3}, {%4,%5,%6,%7}, {%8,%9}, {%0,%1,%2,%3};"
        : "+f"(c[0]), "+f"(c[1]), "+f"(c[2]), "+f"(c[3])
        : "r"(a[0]), "r"(a[1]), "r"(a[2]), "r"(a[3]), "r"(b0), "r"(b1));
}

// ---------------- degree init / histogram -------------------------------------
__global__ void init_kernel() {
    int i = blockIdx.x * blockDim.x + threadIdx.x;
    if (i < N_NODES) { g_deg[i] = 1; g_cur[i] = 0; }   // 1 = self-loop
}

__global__ void hist_kernel(const int* __restrict__ dst) {
    int e = blockIdx.x * blockDim.x + threadIdx.x;
    if (e < N_EDGES) atomicAdd(&g_deg[dst[e]], 1);
}

// single-block exclusive scan of g_deg -> g_off, plus dinv = rsqrt(deg)
__global__ void scan_kernel() {
    __shared__ int wsum[32];
    __shared__ int chunk_total;
    const int tid = threadIdx.x;
    const int lane = tid & 31, wp = tid >> 5;
    int carry = 0;
    for (int base = 0; base < N_NODES; base += 1024) {
        int i = base + tid;
        int v = (i < N_NODES) ? g_deg[i] : 0;
        int x = v;
        #pragma unroll
        for (int o = 1; o < 32; o <<= 1) {
            int t = __shfl_up_sync(0xffffffffu, x, o);
            if (lane >= o) x += t;
        }
        if (lane == 31) wsum[wp] = x;
        __syncthreads();
        if (wp == 0) {
            int s = wsum[lane];
            int y = s;
            #pragma unroll
            for (int o = 1; o < 32; o <<= 1) {
                int t = __shfl_up_sync(0xffffffffu, y, o);
                if (lane >= o) y += t;
            }
            wsum[lane] = y - s;
            if (lane == 31) chunk_total = y;
        }
        __syncthreads();
        int incl = x + wsum[wp];
        if (i < N_NODES) {
            g_off[i]  = carry + incl - v;
            g_dinv[i] = rsqrtf((float)v);
        }
        carry += chunk_total;
        __syncthreads();
    }
    if (tid == 0) g_off[N_NODES] = carry;
}

__global__ void scatter_kernel(const int* __restrict__ src, const int* __restrict__ dst) {
    int e = blockIdx.x * blockDim.x + threadIdx.x;
    if (e >= TOT_EDGES) return;
    int s, d;
    if (e < N_EDGES) { s = src[e]; d = dst[e]; }
    else             { s = d = e - N_EDGES; }
    int pos = g_off[d] + atomicAdd(&g_cur[d], 1);
    g_csr_src[pos] = s;
    g_csr_w[pos]   = g_dinv[s] * g_dinv[d];
}

// ---------------- W1^T hi/lo bf16 precompute (smem transpose) -------------------
// W1 is [512][128] row-major; output [128][512] hi/lo bf16. grid (4,16), block (32,32)
__global__ void w1t_kernel(const float* __restrict__ W1) {
    __shared__ float t[32][33];
    const int n0 = blockIdx.x * 32, k0 = blockIdx.y * 32;
    t[threadIdx.y][threadIdx.x] = W1[(size_t)(k0 + threadIdx.y) * DH + n0 + threadIdx.x];
    __syncthreads();
    float v = t[threadIdx.x][threadIdx.y];     // = W1[k0+tx][n0+ty]
    int n = n0 + threadIdx.y, k = k0 + threadIdx.x;
    __nv_bfloat16 hi = __float2bfloat16(v);
    __nv_bfloat16 lo = __float2bfloat16(v - __bfloat162float(hi));
    g_w1bh[(size_t)n * DIN + k] = hi;
    g_w1bl[(size_t)n * DIN + k] = lo;
}

// ---------------- GEMM1: H1 = X @ W1 via mma.sync bf16 (2-term split) -----------
// CTA: 128 rows x 128 cols, K in 16 chunks of 32. 256 threads = 8 warps (4M x 2N).
__global__ __launch_bounds__(256) void gemm1_mma_kernel(const float* __restrict__ X,
                                                        float* __restrict__ H) {
    // A tiles: [128 rows][32 k] bf16 = 64B rows, 16B-chunk swizzled for ldmatrix
    __shared__ __align__(16) uint8_t sAh[128 * 64];
    __shared__ __align__(16) uint8_t sAl[128 * 64];
    // B tiles: [128 n][32 k] bf16, rows padded to 80B (conflict-free lds.32)
    __shared__ __align__(16) uint8_t sBh[128 * 80];
    __shared__ __align__(16) uint8_t sBl[128 * 80];

    const int tid  = threadIdx.x;
    const int row0 = blockIdx.x * 128;

    float4 xr[4];
    uint4  bhr[2], blr[2];

    // ---- prologue loads (chunk 0) ----
    #pragma unroll
    for (int i = 0; i < 4; i++) {
        int idx = tid + i * 256, row = idx >> 3, kq = idx & 7;
        int gr = row0 + row;
        xr[i] = (gr < N_NODES)
            ? *reinterpret_cast<const float4*>(X + (size_t)gr * DIN + kq * 4)
            : make_float4(0.f, 0.f, 0.f, 0.f);
    }
    #pragma unroll
    for (int i = 0; i < 2; i++) {
        int idx = tid + i * 256, row = idx >> 2, q = idx & 3;
        bhr[i] = *reinterpret_cast<const uint4*>(g_w1bh + (size_t)row * DIN + q * 8);
        blr[i] = *reinterpret_cast<const uint4*>(g_w1bl + (size_t)row * DIN + q * 8);
    }

    const int wid = tid >> 5, lane = tid & 31;
    const int wm = wid & 3, wn = wid >> 2;
    const int g = lane >> 2, tg = lane & 3;
    const int mat = lane >> 3, r8 = lane & 7;

    float acc[2][8][4];
    #pragma unroll
    for (int a = 0; a < 2; a++)
        #pragma unroll
        for (int b = 0; b < 8; b++)
            #pragma unroll
            for (int c = 0; c < 4; c++) acc[a][b][c] = 0.f;

    const uint32_t aAh = smem_u32(sAh), aAl = smem_u32(sAl);

    #pragma unroll 1
    for (int c = 0; c < DIN / 32; c++) {
        // ---- store staged regs to smem ----
        #pragma unroll
        for (int i = 0; i < 4; i++) {
            int idx = tid + i * 256, row = idx >> 3, kq = idx & 7;
            int chunk = kq >> 1, sub = kq & 1;
            int sc = chunk ^ ((row >> 1) & 3);
            int off = row * 64 + sc * 16 + sub * 8;
            float4 v = xr[i];
            __nv_bfloat16 h0 = __float2bfloat16(v.x), h1 = __float2bfloat16(v.y);
            __nv_bfloat16 h2 = __float2bfloat16(v.z), h3 = __float2bfloat16(v.w);
            __nv_bfloat16 l0 = __float2bfloat16(v.x - __bfloat162float(h0));
            __nv_bfloat16 l1 = __float2bfloat16(v.y - __bfloat162float(h1));
            __nv_bfloat16 l2 = __float2bfloat16(v.z - __bfloat162float(h2));
            __nv_bfloat16 l3 = __float2bfloat16(v.w - __bfloat162float(h3));
            uint2 whi = make_uint2(pack_bf16(h0, h1), pack_bf16(h2, h3));
            uint2 wlo = make_uint2(pack_bf16(l0, l1), pack_bf16(l2, l3));
            *reinterpret_cast<uint2*>(sAh + off) = whi;
            *reinterpret_cast<uint2*>(sAl + off) = wlo;
        }
        #pragma unroll
        for (int i = 0; i < 2; i++) {
            int idx = tid + i * 256, row = idx >> 2, q = idx & 3;
            *reinterpret_cast<uint4*>(sBh + row * 80 + q * 16) = bhr[i];
            *reinterpret_cast<uint4*>(sBl + row * 80 + q * 16) = blr[i];
        }
        __syncthreads();

        // ---- prefetch next chunk into regs (overlaps MMAs) ----
        if (c + 1 < DIN / 32) {
            const int k0 = (c + 1) * 32;
            #pragma unroll
            for (int i = 0; i < 4; i++) {
                int idx = tid + i * 256, row = idx >> 3, kq = idx & 7;
                int gr = row0 + row;
                xr[i] = (gr < N_NODES)
                    ? *reinterpret_cast<const float4*>(X + (size_t)gr * DIN + k0 + kq * 4)
                    : make_float4(0.f, 0.f, 0.f, 0.f);
            }
            #pragma unroll
            for (int i = 0; i < 2; i++) {
                int idx = tid + i * 256, row = idx >> 2, q = idx & 3;
                bhr[i] = *reinterpret_cast<const uint4*>(g_w1bh + (size_t)row * DIN + k0 + q * 8);
                blr[i] = *reinterpret_cast<const uint4*>(g_w1bl + (size_t)row * DIN + k0 + q * 8);
            }
        }

        // ---- MMAs over this chunk (2 k16-tiles) ----
        #pragma unroll
        for (int kt = 0; kt < 2; kt++) {
            uint32_t ah[2][4], al[2][4];
            #pragma unroll
            for (int mt = 0; mt < 2; mt++) {
                int arow = wm * 32 + mt * 16 + r8 + (mat & 1) * 8;
                int chunk = 2 * kt + (mat >> 1);
                int sc = chunk ^ ((arow >> 1) & 3);
                uint32_t off = (uint32_t)(arow * 64 + sc * 16);
                ldmat4(ah[mt], aAh + off);
                ldmat4(al[mt], aAl + off);
            }
            #pragma unroll
            for (int nt = 0; nt < 8; nt++) {
                int n = wn * 64 + nt * 8 + g;
                uint32_t boff = (uint32_t)(n * 80 + kt * 32 + tg * 4);
                uint32_t bh0 = *reinterpret_cast<const uint32_t*>(sBh + boff);
                uint32_t bh1 = *reinterpret_cast<const uint32_t*>(sBh + boff + 16);
                uint32_t bl0 = *reinterpret_cast<const uint32_t*>(sBl + boff);
                uint32_t bl1 = *reinterpret_cast<const uint32_t*>(sBl + boff + 16);
                #pragma unroll
                for (int mt = 0; mt < 2; mt++) {
                    mma_bf16(acc[mt][nt], ah[mt], bh0, bh1);
                    mma_bf16(acc[mt][nt], ah[mt], bl0, bl1);
                    mma_bf16(acc[mt][nt], al[mt], bh0, bh1);
                }
            }
        }
        __syncthreads();
    }

    // ---- epilogue ----
    #pragma unroll
    for (int mt = 0; mt < 2; mt++) {
        int r0 = row0 + wm * 32 + mt * 16 + g;
        #pragma unroll
        for (int nt = 0; nt < 8; nt++) {
            int colb = wn * 64 + nt * 8 + tg * 2;
            if (r0 < N_NODES)
                *reinterpret_cast<float2*>(H + (size_t)r0 * DH + colb) =
                    make_float2(acc[mt][nt][0], acc[mt][nt][1]);
            if (r0 + 8 < N_NODES)
                *reinterpret_cast<float2*>(H + (size_t)(r0 + 8) * DH + colb) =
                    make_float2(acc[mt][nt][2], acc[mt][nt][3]);
        }
    }
}

// ---------------- Agg1: a1 = relu(A_hat @ h1 + b1), warp per node --------------
__global__ void agg1_kernel(const float* __restrict__ b1) {
    int gw = (blockIdx.x * blockDim.x + threadIdx.x) >> 5;
    int lane = threadIdx.x & 31;
    if (gw >= N_NODES) return;
    int beg = g_off[gw], end = g_off[gw + 1];
    float4 acc = make_float4(0.f, 0.f, 0.f, 0.f);
    for (int p = beg; p < end; ++p) {
        int   s = g_csr_src[p];
        float w = g_csr_w[p];
        float4 hv = *reinterpret_cast<const float4*>(g_h1 + (size_t)s * DH + lane * 4);
        acc.x += w * hv.x; acc.y += w * hv.y; acc.z += w * hv.z; acc.w += w * hv.w;
    }
    float4 bv = *reinterpret_cast<const float4*>(b1 + lane * 4);
    acc.x = fmaxf(acc.x + bv.x, 0.f);
    acc.y = fmaxf(acc.y + bv.y, 0.f);
    acc.z = fmaxf(acc.z + bv.z, 0.f);
    acc.w = fmaxf(acc.w + bv.w, 0.f);
    *reinterpret_cast<float4*>(g_a1 + (size_t)gw * DH + lane * 4) = acc;
}

// ---------------- GEMM2: h2 = a1 @ W2, smem-staged --------------------------------
#define G2_SMEM ((128 * 132 + DH * DOUT) * 4)
__global__ __launch_bounds__(256) void gemm2_kernel(const float* __restrict__ W2) {
    extern __shared__ float s2[];
    float* sA = s2;                  // [128][132]
    float* sW = s2 + 128 * 132;      // [128][40]
    const int tid = threadIdx.x;
    const int row0 = blockIdx.x * 128;

    for (int j = tid; j < DH * DOUT; j += 256) sW[j] = W2[j];
    #pragma unroll
    for (int i = 0; i < 16; i++) {
        int idx = tid + i * 256, row = idx >> 5, kq = idx & 31;
        int gr = row0 + row;
        float4 v = (gr < N_NODES)
            ? *reinterpret_cast<const float4*>(g_a1 + (size_t)gr * DH + kq * 4)
            : make_float4(0.f, 0.f, 0.f, 0.f);
        *reinterpret_cast<float4*>(sA + row * 132 + kq * 4) = v;
    }
    __syncthreads();

    const int rg = tid >> 1;          // row 0..127
    const int cg = tid & 1;           // 20 cols each
    float acc[20];
    #pragma unroll
    for (int j = 0; j < 20; j++) acc[j] = 0.f;

    #pragma unroll 4
    for (int k = 0; k < DH; k++) {
        float a = sA[rg * 132 + k];
        const float* wrow = &sW[k * DOUT + cg * 20];
        #pragma unroll
        for (int j = 0; j < 20; j++) acc[j] += a * wrow[j];
    }

    int r = row0 + rg;
    if (r < N_NODES) {
        float* out = g_h2 + (size_t)r * DOUT + cg * 20;
        #pragma unroll
        for (int j = 0; j < 20; j++) out[j] = acc[j];
    }
}

// ---------------- Agg2: out_h = A_hat @ h2 + b2, warp per node -----------------
__global__ void agg2_kernel(const float* __restrict__ b2, float* __restrict__ out) {
    int gw = (blockIdx.x * blockDim.x + threadIdx.x) >> 5;
    int lane = threadIdx.x & 31;
    if (gw >= N_NODES) return;
    int beg = g_off[gw], end = g_off[gw + 1];
    float acc0 = 0.f, acc1 = 0.f;
    bool has2 = lane < (DOUT - 32);
    for (int p = beg; p < end; ++p) {
        int   s = g_csr_src[p];
        float w = g_csr_w[p];
        const float* row = g_h2 + (size_t)s * DOUT;
        acc0 += w * row[lane];
        if (has2) acc1 += w * row[32 + lane];
    }
    float* orow = out + (size_t)gw * DOUT;
    orow[lane] = acc0 + b2[lane];
    if (has2) orow[32 + lane] = acc1 + b2[32 + lane];
}

// ---------------- log_softmax over DOUT=40, warp per node ----------------------
__global__ void logsoftmax_kernel(const float* __restrict__ h, float* __restrict__ out) {
    int gw = (blockIdx.x * blockDim.x + threadIdx.x) >> 5;
    int lane = threadIdx.x & 31;
    if (gw >= N_NODES) return;
    const float* row = h + (size_t)gw * DOUT;
    bool has2 = lane < (DOUT - 32);
    float v0 = row[lane];
    float v1 = has2 ? row[32 + lane] : -INFINITY;
    float m = fmaxf(v0, v1);
    #pragma unroll
    for (int o = 16; o > 0; o >>= 1) m = fmaxf(m, __shfl_xor_sync(0xffffffffu, m, o));
    float e = expf(v0 - m) + (has2 ? expf(v1 - m) : 0.f);
    #pragma unroll
    for (int o = 16; o > 0; o >>= 1) e += __shfl_xor_sync(0xffffffffu, e, o);
    float lse = m + logf(e);
    float* orow = out + (size_t)gw * DOUT;
    orow[lane] = v0 - lse;
    if (has2) orow[32 + lane] = v1 - lse;
}

// ---------------- launch --------------------------------------------------------
extern "C" void kernel_launch(void* const* d_in, const int* in_sizes, int n_in,
                              void* d_out, int out_size) {
    const float* x   = (const float*)d_in[0];
    const int*   ei  = (const int*)  d_in[1];   // [2,E] row-major
    const float* W1  = (const float*)d_in[2];
    const float* b1  = (const float*)d_in[3];
    const float* W2  = (const float*)d_in[4];
    const float* b2  = (const float*)d_in[5];
    float* out = (float*)d_out;

    const int* src = ei;
    const int* dst = ei + N_EDGES;

    float* h1;  cudaGetSymbolAddress((void**)&h1, g_h1);

    cudaFuncSetAttribute(gemm2_kernel, cudaFuncAttributeMaxDynamicSharedMemorySize, G2_SMEM);

    init_kernel<<<(N_NODES + 255) / 256, 256>>>();
    hist_kernel<<<(N_EDGES + 255) / 256, 256>>>(dst);
    scan_kernel<<<1, 1024>>>();
    scatter_kernel<<<(TOT_EDGES + 255) / 256, 256>>>(src, dst);

    w1t_kernel<<<dim3(4, 16), dim3(32, 32)>>>(W1);
    gemm1_mma_kernel<<<(N_NODES + 127) / 128, 256>>>(x, h1);
    agg1_kernel<<<(N_NODES * 32 + 255) / 256, 256>>>(b1);
    gemm2_kernel<<<(N_NODES + 127) / 128, 256, G2_SMEM>>>(W2);

    // out = [h (N*DOUT) | log_softmax(h) (N*DOUT)]
    agg2_kernel<<<(N_NODES * 32 + 255) / 256, 256>>>(b2, out);
    if (out_size >= 2 * N_NODES * DOUT) {
        logsoftmax_kernel<<<(N_NODES * 32 + 255) / 256, 256>>>(out, out + (size_t)N_NODES * DOUT);
    }
}

// round 4
// speedup vs baseline: 1.8140x; 1.2268x over previous
#include <cuda_runtime.h>
#include <cuda_bf16.h>
#include <math.h>
#include <stdint.h>

#define N_NODES 100000
#define N_EDGES 1600000
#define DIN 512
#define DH 128
#define DOUT 40
#define TOT_EDGES (N_EDGES + N_NODES)

// ---------------- scratch (device globals; no runtime allocation) -------------
__device__ int   g_deg[N_NODES];
__device__ int   g_off[N_NODES + 1];
__device__ int   g_cur[N_NODES];
__device__ float g_dinv[N_NODES];
__device__ __align__(16) int2  g_csr[TOT_EDGES];              // (src, w bits)
__device__ __align__(16) float g_h1[(size_t)N_NODES * DH];    // X @ W1 (pre-agg)
__device__ __align__(16) float g_a1[(size_t)N_NODES * DH];    // relu(agg(h1) + b1)
__device__ __align__(16) float g_h2[(size_t)N_NODES * DOUT];  // a1 @ W2 (pre-agg)
__device__ __align__(16) float g_w1t[(size_t)DH * DIN];       // W1^T tf32-rounded, [n][k]
__device__ __align__(16) float g_w2t[(size_t)DOUT * DH];      // W2^T tf32-rounded, [n][k]

// ---------------- helpers -------------------------------------------------------
__device__ __forceinline__ float tf32r(float x) {
    uint32_t u;
    asm("cvt.rna.tf32.f32 %0, %1;" : "=r"(u) : "f"(x));
    return __uint_as_float(u);
}

__device__ __forceinline__ void mma_tf32(float* c, const uint32_t* a, uint32_t b0, uint32_t b1) {
    asm volatile(
        "mma.sync.aligned.m16n8k8.row.col.f32.tf32.tf32.f32 "
        "{%0,%1,%2,%3}, {%4,%5,%6,%7}, {%8,%9}, {%0,%1,%2,%3};"
        : "+f"(c[0]), "+f"(c[1]), "+f"(c[2]), "+f"(c[3])
        : "r"(a[0]), "r"(a[1]), "r"(a[2]), "r"(a[3]), "r"(b0), "r"(b1));
}

// ---------------- degree init / histogram -------------------------------------
__global__ void init_kernel() {
    int i = blockIdx.x * blockDim.x + threadIdx.x;
    if (i < N_NODES) g_deg[i] = 1;   // 1 = self-loop
}

__global__ void hist_kernel(const int* __restrict__ dst) {
    int e = blockIdx.x * blockDim.x + threadIdx.x;
    if (e < N_EDGES) atomicAdd(&g_deg[dst[e]], 1);
}

// single-block exclusive scan of g_deg -> g_off (+ g_cur), plus dinv = rsqrt(deg)
__global__ void scan_kernel() {
    __shared__ int wsum[32];
    __shared__ int chunk_total;
    const int tid = threadIdx.x;
    const int lane = tid & 31, wp = tid >> 5;
    int carry = 0;
    for (int base = 0; base < N_NODES; base += 1024) {
        int i = base + tid;
        int v = (i < N_NODES) ? g_deg[i] : 0;
        int x = v;
        #pragma unroll
        for (int o = 1; o < 32; o <<= 1) {
            int t = __shfl_up_sync(0xffffffffu, x, o);
            if (lane >= o) x += t;
        }
        if (lane == 31) wsum[wp] = x;
        __syncthreads();
        if (wp == 0) {
            int s = wsum[lane];
            int y = s;
            #pragma unroll
            for (int o = 1; o < 32; o <<= 1) {
                int t = __shfl_up_sync(0xffffffffu, y, o);
                if (lane >= o) y += t;
            }
            wsum[lane] = y - s;
            if (lane == 31) chunk_total = y;
        }
        __syncthreads();
        int incl = x + wsum[wp];
        if (i < N_NODES) {
            int off = carry + incl - v;
            g_off[i] = off;
            g_cur[i] = off;
            g_dinv[i] = rsqrtf((float)v);
        }
        carry += chunk_total;
        __syncthreads();
    }
    if (tid == 0) g_off[N_NODES] = carry;
}

__global__ void scatter_kernel(const int* __restrict__ src, const int* __restrict__ dst) {
    int e = blockIdx.x * blockDim.x + threadIdx.x;
    if (e >= TOT_EDGES) return;
    int s, d;
    if (e < N_EDGES) { s = src[e]; d = dst[e]; }
    else             { s = d = e - N_EDGES; }
    int pos = atomicAdd(&g_cur[d], 1);
    g_csr[pos] = make_int2(s, __float_as_int(g_dinv[s] * g_dinv[d]));
}

// ---------------- W^T tf32 precompute (smem transpose) --------------------------
// W1 [512][128] -> g_w1t [128][512]. grid (4,16), block (32,32)
__global__ void w1t_kernel(const float* __restrict__ W1) {
    __shared__ float t[32][33];
    const int n0 = blockIdx.x * 32, k0 = blockIdx.y * 32;
    t[threadIdx.y][threadIdx.x] = W1[(size_t)(k0 + threadIdx.y) * DH + n0 + threadIdx.x];
    __syncthreads();
    float v = t[threadIdx.x][threadIdx.y];
    g_w1t[(size_t)(n0 + threadIdx.y) * DIN + k0 + threadIdx.x] = tf32r(v);
}

// W2 [128][40] -> g_w2t [40][128]. single block 1024 threads
__global__ void w2t_kernel(const float* __restrict__ W2) {
    int idx = threadIdx.x + blockIdx.x * blockDim.x;
    if (idx >= DH * DOUT) return;
    int k = idx / DOUT, n = idx % DOUT;
    g_w2t[(size_t)n * DH + k] = tf32r(W2[idx]);
}

// ---------------- GEMM1: H1 = X @ W1 via mma.sync tf32 --------------------------
// CTA: 128 rows x 128 cols, K in 16 chunks of 32. 256 threads = 8 warps (4M x 2N).
__global__ __launch_bounds__(256) void gemm1_tf32_kernel(const float* __restrict__ X,
                                                         float* __restrict__ H) {
    __shared__ __align__(16) float sA[128 * 36];   // [row][k] pad 36
    __shared__ __align__(16) float sB[128 * 36];   // [n][k]   pad 36

    const int tid  = threadIdx.x;
    const int row0 = blockIdx.x * 128;

    float4 xr[4], br[4];
    // prologue (chunk 0)
    #pragma unroll
    for (int i = 0; i < 4; i++) {
        int idx = tid + i * 256, row = idx >> 3, kq = idx & 7;
        int gr = row0 + row;
        xr[i] = (gr < N_NODES)
            ? *reinterpret_cast<const float4*>(X + (size_t)gr * DIN + kq * 4)
            : make_float4(0.f, 0.f, 0.f, 0.f);
        br[i] = *reinterpret_cast<const float4*>(g_w1t + (size_t)row * DIN + kq * 4);
    }

    const int wid = tid >> 5, lane = tid & 31;
    const int wm = wid & 3, wn = wid >> 2;
    const int g = lane >> 2, tg = lane & 3;

    float acc[2][8][4];
    #pragma unroll
    for (int a = 0; a < 2; a++)
        #pragma unroll
        for (int b = 0; b < 8; b++)
            #pragma unroll
            for (int c = 0; c < 4; c++) acc[a][b][c] = 0.f;

    #pragma unroll 1
    for (int c = 0; c < DIN / 32; c++) {
        // store staged regs (A converted to tf32)
        #pragma unroll
        for (int i = 0; i < 4; i++) {
            int idx = tid + i * 256, row = idx >> 3, kq = idx & 7;
            float4 v = xr[i];
            v.x = tf32r(v.x); v.y = tf32r(v.y); v.z = tf32r(v.z); v.w = tf32r(v.w);
            *reinterpret_cast<float4*>(sA + row * 36 + kq * 4) = v;
            *reinterpret_cast<float4*>(sB + row * 36 + kq * 4) = br[i];
        }
        __syncthreads();

        // prefetch next chunk
        if (c + 1 < DIN / 32) {
            const int k0 = (c + 1) * 32;
            #pragma unroll
            for (int i = 0; i < 4; i++) {
                int idx = tid + i * 256, row = idx >> 3, kq = idx & 7;
                int gr = row0 + row;
                xr[i] = (gr < N_NODES)
                    ? *reinterpret_cast<const float4*>(X + (size_t)gr * DIN + k0 + kq * 4)
                    : make_float4(0.f, 0.f, 0.f, 0.f);
                br[i] = *reinterpret_cast<const float4*>(g_w1t + (size_t)row * DIN + k0 + kq * 4);
            }
        }

        // MMAs over this chunk: 4 k8 tiles
        #pragma unroll
        for (int kt = 0; kt < 4; kt++) {
            const int kk = kt * 8;
            uint32_t a[2][4];
            #pragma unroll
            for (int mt = 0; mt < 2; mt++) {
                const float* pa = sA + (wm * 32 + mt * 16 + g) * 36 + kk + tg;
                a[mt][0] = __float_as_uint(pa[0]);
                a[mt][1] = __float_as_uint(pa[8 * 36]);
                a[mt][2] = __float_as_uint(pa[4]);
                a[mt][3] = __float_as_uint(pa[8 * 36 + 4]);
            }
            #pragma unroll
            for (int nt = 0; nt < 8; nt++) {
                const float* pb = sB + (wn * 64 + nt * 8 + g) * 36 + kk + tg;
                uint32_t b0 = __float_as_uint(pb[0]);
                uint32_t b1 = __float_as_uint(pb[4]);
                mma_tf32(acc[0][nt], a[0], b0, b1);
                mma_tf32(acc[1][nt], a[1], b0, b1);
            }
        }
        __syncthreads();
    }

    // epilogue
    #pragma unroll
    for (int mt = 0; mt < 2; mt++) {
        int r0 = row0 + wm * 32 + mt * 16 + g;
        #pragma unroll
        for (int nt = 0; nt < 8; nt++) {
            int colb = wn * 64 + nt * 8 + tg * 2;
            if (r0 < N_NODES)
                *reinterpret_cast<float2*>(H + (size_t)r0 * DH + colb) =
                    make_float2(acc[mt][nt][0], acc[mt][nt][1]);
            if (r0 + 8 < N_NODES)
                *reinterpret_cast<float2*>(H + (size_t)(r0 + 8) * DH + colb) =
                    make_float2(acc[mt][nt][2], acc[mt][nt][3]);
        }
    }
}

// ---------------- Agg1: a1 = relu(A_hat @ h1 + b1), warp per node --------------
__global__ void agg1_kernel(const float* __restrict__ b1) {
    int gw = (blockIdx.x * blockDim.x + threadIdx.x) >> 5;
    int lane = threadIdx.x & 31;
    if (gw >= N_NODES) return;
    int beg = g_off[gw], end = g_off[gw + 1];
    float4 acc = make_float4(0.f, 0.f, 0.f, 0.f);
    for (int p = beg; p < end; ++p) {
        int2  e = g_csr[p];
        float w = __int_as_float(e.y);
        float4 hv = *reinterpret_cast<const float4*>(g_h1 + (size_t)e.x * DH + lane * 4);
        acc.x += w * hv.x; acc.y += w * hv.y; acc.z += w * hv.z; acc.w += w * hv.w;
    }
    float4 bv = *reinterpret_cast<const float4*>(b1 + lane * 4);
    acc.x = fmaxf(acc.x + bv.x, 0.f);
    acc.y = fmaxf(acc.y + bv.y, 0.f);
    acc.z = fmaxf(acc.z + bv.z, 0.f);
    acc.w = fmaxf(acc.w + bv.w, 0.f);
    *reinterpret_cast<float4*>(g_a1 + (size_t)gw * DH + lane * 4) = acc;
}

// ---------------- GEMM2: h2 = a1 @ W2 via mma.sync tf32 --------------------------
// CTA: 128 rows x 40 cols, K=128 all in smem. 128 threads = 4 warps (4M).
#define G2_SMEM ((128 * 132 + 40 * 132) * 4)
__global__ __launch_bounds__(128) void gemm2_tf32_kernel() {
    extern __shared__ float s2[];
    float* sA = s2;                 // [128][132]
    float* sB = s2 + 128 * 132;     // [40][132]
    const int tid  = threadIdx.x;
    const int row0 = blockIdx.x * 128;

    #pragma unroll
    for (int i = 0; i < 32; i++) {
        int idx = tid + i * 128, row = idx >> 5, kq = idx & 31;
        int gr = row0 + row;
        float4 v = (gr < N_NODES)
            ? *reinterpret_cast<const float4*>(g_a1 + (size_t)gr * DH + kq * 4)
            : make_float4(0.f, 0.f, 0.f, 0.f);
        v.x = tf32r(v.x); v.y = tf32r(v.y); v.z = tf32r(v.z); v.w = tf32r(v.w);
        *reinterpret_cast<float4*>(sA + row * 132 + kq * 4) = v;
    }
    #pragma unroll
    for (int i = 0; i < 10; i++) {
        int idx = tid + i * 128, row = idx >> 5, kq = idx & 31;
        float4 v = *reinterpret_cast<const float4*>(g_w2t + (size_t)row * DH + kq * 4);
        *reinterpret_cast<float4*>(sB + row * 132 + kq * 4) = v;
    }
    __syncthreads();

    const int wid = tid >> 5, lane = tid & 31;
    const int g = lane >> 2, tg = lane & 3;

    float acc[2][5][4];
    #pragma unroll
    for (int a = 0; a < 2; a++)
        #pragma unroll
        for (int b = 0; b < 5; b++)
            #pragma unroll
            for (int c = 0; c < 4; c++) acc[a][b][c] = 0.f;

    #pragma unroll
    for (int kt = 0; kt < DH / 8; kt++) {
        const int kk = kt * 8;
        uint32_t a[2][4];
        #pragma unroll
        for (int mt = 0; mt < 2; mt++) {
            const float* pa = sA + (wid * 32 + mt * 16 + g) * 132 + kk + tg;
            a[mt][0] = __float_as_uint(pa[0]);
            a[mt][1] = __float_as_uint(pa[8 * 132]);
            a[mt][2] = __float_as_uint(pa[4]);
            a[mt][3] = __float_as_uint(pa[8 * 132 + 4]);
        }
        #pragma unroll
        for (int nt = 0; nt < 5; nt++) {
            const float* pb = sB + (nt * 8 + g) * 132 + kk + tg;
            uint32_t b0 = __float_as_uint(pb[0]);
            uint32_t b1 = __float_as_uint(pb[4]);
            mma_tf32(acc[0][nt], a[0], b0, b1);
            mma_tf32(acc[1][nt], a[1], b0, b1);
        }
    }

    #pragma unroll
    for (int mt = 0; mt < 2; mt++) {
        int r0 = row0 + wid * 32 + mt * 16 + g;
        #pragma unroll
        for (int nt = 0; nt < 5; nt++) {
            int colb = nt * 8 + tg * 2;
            if (r0 < N_NODES)
                *reinterpret_cast<float2*>(g_h2 + (size_t)r0 * DOUT + colb) =
                    make_float2(acc[mt][nt][0], acc[mt][nt][1]);
            if (r0 + 8 < N_NODES)
                *reinterpret_cast<float2*>(g_h2 + (size_t)(r0 + 8) * DOUT + colb) =
                    make_float2(acc[mt][nt][2], acc[mt][nt][3]);
        }
    }
}

// ---------------- Agg2 + b2 + log_softmax fused, warp per node -------------------
__global__ void agg2_lsm_kernel(const float* __restrict__ b2, float* __restrict__ out,
                                int do_lsm) {
    int gw = (blockIdx.x * blockDim.x + threadIdx.x) >> 5;
    int lane = threadIdx.x & 31;
    if (gw >= N_NODES) return;
    int beg = g_off[gw], end = g_off[gw + 1];
    float acc0 = 0.f, acc1 = 0.f;
    bool has2 = lane < (DOUT - 32);
    for (int p = beg; p < end; ++p) {
        int2  e = g_csr[p];
        float w = __int_as_float(e.y);
        const float* row = g_h2 + (size_t)e.x * DOUT;
        acc0 += w * row[lane];
        if (has2) acc1 += w * row[32 + lane];
    }
    acc0 += b2[lane];
    if (has2) acc1 += b2[32 + lane];

    float* orow = out + (size_t)gw * DOUT;
    orow[lane] = acc0;
    if (has2) orow[32 + lane] = acc1;

    if (do_lsm) {
        float m = fmaxf(acc0, has2 ? acc1 : -INFINITY);
        #pragma unroll
        for (int o = 16; o > 0; o >>= 1) m = fmaxf(m, __shfl_xor_sync(0xffffffffu, m, o));
        float e = expf(acc0 - m) + (has2 ? expf(acc1 - m) : 0.f);
        #pragma unroll
        for (int o = 16; o > 0; o >>= 1) e += __shfl_xor_sync(0xffffffffu, e, o);
        float lse = m + logf(e);
        float* lrow = out + (size_t)N_NODES * DOUT + (size_t)gw * DOUT;
        lrow[lane] = acc0 - lse;
        if (has2) lrow[32 + lane] = acc1 - lse;
    }
}

// ---------------- launch --------------------------------------------------------
extern "C" void kernel_launch(void* const* d_in, const int* in_sizes, int n_in,
                              void* d_out, int out_size) {
    const float* x   = (const float*)d_in[0];
    const int*   ei  = (const int*)  d_in[1];   // [2,E] row-major
    const float* W1  = (const float*)d_in[2];
    const float* b1  = (const float*)d_in[3];
    const float* W2  = (const float*)d_in[4];
    const float* b2  = (const float*)d_in[5];
    float* out = (float*)d_out;

    const int* src = ei;
    const int* dst = ei + N_EDGES;

    float* h1;  cudaGetSymbolAddress((void**)&h1, g_h1);

    cudaFuncSetAttribute(gemm2_tf32_kernel, cudaFuncAttributeMaxDynamicSharedMemorySize,
                         G2_SMEM);

    init_kernel<<<(N_NODES + 255) / 256, 256>>>();
    hist_kernel<<<(N_EDGES + 255) / 256, 256>>>(dst);
    scan_kernel<<<1, 1024>>>();
    scatter_kernel<<<(TOT_EDGES + 255) / 256, 256>>>(src, dst);

    w1t_kernel<<<dim3(4, 16), dim3(32, 32)>>>(W1);
    w2t_kernel<<<(DH * DOUT + 1023) / 1024, 1024>>>(W2);

    gemm1_tf32_kernel<<<(N_NODES + 127) / 128, 256>>>(x, h1);
    agg1_kernel<<<(N_NODES * 32 + 255) / 256, 256>>>(b1);
    gemm2_tf32_kernel<<<(N_NODES + 127) / 128, 128, G2_SMEM>>>();

    int do_lsm = (out_size >= 2 * N_NODES * DOUT) ? 1 : 0;
    agg2_lsm_kernel<<<(N_NODES * 32 + 255) / 256, 256>>>(b2, out, do_lsm);
}